// round 11
// baseline (speedup 1.0000x reference)
#include <cuda_runtime.h>
#include <math.h>

#define BB 16384
#define HH 128
#define TT 20
#define PRED 30
#define G4 512          // 4*H gates
#define MT 32           // batch rows per block
#define KC 8            // k-chunk (double buffered)
#define NCHUNK (HH / KC)   // 16
#define NTHREADS 256

struct StepParams {
    const float* x;        // [B,2] input this step
    const float* Wih;      // [512,2]
    const float* Whh;      // [512,128]
    const float* bih;      // [512]
    const float* bhh;      // [512]
    float* h;              // [B,128] in/out
    float* c;              // [B,128] in/out
    float* fc_state;       // decoder: next-step input buffer [B,2] (else null)
    float* fc_out;         // decoder: output slice [B,2] (else null)
};

// persistent state (device globals -> no allocation)
__device__ float g_hpo[BB * HH];
__device__ float g_cpo[BB * HH];
__device__ float g_hsp[BB * HH];
__device__ float g_csp[BB * HH];
__device__ float g_hds[BB * HH];
__device__ float g_cds[BB * HH];
__device__ float g_cs[BB * 2];
__device__ float g_cp[BB * 2];

__device__ __forceinline__ float sigmoidf_(float x) { return 1.0f / (1.0f + expf(-x)); }

// ---- packed f32x2 helpers (Blackwell FFMA2 path) ----
__device__ __forceinline__ unsigned long long pk2(float lo, float hi) {
    unsigned long long r;
    asm("mov.b64 %0, {%1, %2};" : "=l"(r) : "f"(lo), "f"(hi));
    return r;
}
__device__ __forceinline__ unsigned long long pkdup(float v) {
    unsigned long long r;
    asm("mov.b64 %0, {%1, %1};" : "=l"(r) : "f"(v));
    return r;
}
__device__ __forceinline__ void upk2(unsigned long long v, float& lo, float& hi) {
    asm("mov.b64 {%0, %1}, %2;" : "=f"(lo), "=f"(hi) : "l"(v));
}
__device__ __forceinline__ void fma2(unsigned long long& d, unsigned long long a, unsigned long long b) {
    asm("fma.rn.f32x2 %0, %1, %2, %0;" : "+l"(d) : "l"(a), "l"(b));
}

// Warp ownership remap (crossbar-redundancy fix):
//   warp w: gh = w&1 (gate half), rg = w>>1 (row group of 8 rows)
//   thread owns hidden pair j0 = 64*gh + 2*lane (+1), all 4 gate types:
//   gate(s) = 128*s + j0, j0+1  -> W read = 4x LDS.64 per k (2 warps/gate column)
//   acc2[r][s] packs the gate pair as f32x2.
__global__ __launch_bounds__(NTHREADS, 2)
void lstm_step_kernel(StepParams pa, StepParams pb,
                      const float* __restrict__ Wfc, const float* __restrict__ bfc,
                      int first)
{
    const StepParams p = blockIdx.y ? pb : pa;

    __shared__ float As[MT][HH];          // h tile (broadcast A reads); aliased as FC scratch after GEMM
    __shared__ float Ws[2][KC][G4];       // W chunk, double buffered, [k][gate]

    const int tid  = threadIdx.x;
    const int lane = tid & 31;
    const int warp = tid >> 5;
    const int gh   = warp & 1;            // gate half (0: gates j<64, 1: j>=64 within each type)
    const int rg   = warp >> 1;           // row group: rows rg*8 .. rg*8+7
    const int row0 = blockIdx.x * MT;
    const int j0   = 64 * gh + 2 * lane;  // hidden pair base

    unsigned long long acc2[8][4];        // [row r][gate type s], f32x2 over (j0, j0+1)

    // ---- init accumulators: bias + input-term (x is [*,2]) ----
    {
        float x0[8], x1[8];
#pragma unroll
        for (int r = 0; r < 8; ++r) {
            int b = row0 + rg * 8 + r;
            float2 xv = *reinterpret_cast<const float2*>(&p.x[b * 2]);
            x0[r] = xv.x; x1[r] = xv.y;
        }
#pragma unroll
        for (int s = 0; s < 4; ++s) {
            int gp = 128 * s + j0;
            float2 bi = *reinterpret_cast<const float2*>(&p.bih[gp]);
            float2 bh = *reinterpret_cast<const float2*>(&p.bhh[gp]);
            float4 wi = *reinterpret_cast<const float4*>(&p.Wih[2 * gp]);  // {w(j0,0),w(j0,1),w(j0+1,0),w(j0+1,1)}
            float b0 = bi.x + bh.x, b1 = bi.y + bh.y;
#pragma unroll
            for (int r = 0; r < 8; ++r) {
                float v0 = fmaf(x1[r], wi.y, fmaf(x0[r], wi.x, b0));
                float v1 = fmaf(x1[r], wi.w, fmaf(x0[r], wi.z, b1));
                acc2[r][s] = pk2(v0, v1);
            }
        }
    }

    // ---- recurrent GEMM: acc += h_tile @ Whh^T (f32x2 packed FMAs) ----
    if (!first) {
        // stage h tile
        {
            float4* As4 = reinterpret_cast<float4*>(&As[0][0]);
            const float4* h4 = reinterpret_cast<const float4*>(p.h + (size_t)row0 * HH);
#pragma unroll
            for (int i = 0; i < (MT * HH / 4) / NTHREADS; ++i)   // 4 iters
                As4[tid + i * NTHREADS] = h4[tid + i * NTHREADS];
        }

        // per-thread W chunk staging: 4 x float4 = 16 floats per chunk
        float4 wreg[4];
        const int wg[4] = { (tid + 0*NTHREADS) >> 1, (tid + 1*NTHREADS) >> 1,
                            (tid + 2*NTHREADS) >> 1, (tid + 3*NTHREADS) >> 1 };
        const int wkf  = tid & 1;

#pragma unroll
        for (int i = 0; i < 4; ++i)
            wreg[i] = *reinterpret_cast<const float4*>(&p.Whh[wg[i] * HH + 0 + wkf * 4]);
#pragma unroll
        for (int i = 0; i < 4; ++i) {
            Ws[0][wkf * 4 + 0][wg[i]] = wreg[i].x;
            Ws[0][wkf * 4 + 1][wg[i]] = wreg[i].y;
            Ws[0][wkf * 4 + 2][wg[i]] = wreg[i].z;
            Ws[0][wkf * 4 + 3][wg[i]] = wreg[i].w;
        }
        __syncthreads();

        for (int ch = 0; ch < NCHUNK; ++ch) {
            const int buf = ch & 1;
            // prefetch next chunk into registers (overlapped with compute below)
            if (ch < NCHUNK - 1) {
                int k0n = (ch + 1) * KC;
#pragma unroll
                for (int i = 0; i < 4; ++i)
                    wreg[i] = *reinterpret_cast<const float4*>(&p.Whh[wg[i] * HH + k0n + wkf * 4]);
            }

            // compute this chunk: KC k's in groups of 4
#pragma unroll
            for (int kk4 = 0; kk4 < KC / 4; ++kk4) {
                float4 a4[8];   // broadcast reads: one per row of this warp's row group
#pragma unroll
                for (int r = 0; r < 8; ++r)
                    a4[r] = *reinterpret_cast<const float4*>(&As[rg * 8 + r][ch * KC + kk4 * 4]);
#pragma unroll
                for (int t = 0; t < 4; ++t) {
                    unsigned long long w2[4];   // one f32x2 gate-pair per type
#pragma unroll
                    for (int s = 0; s < 4; ++s)
                        w2[s] = *reinterpret_cast<const unsigned long long*>(&Ws[buf][kk4 * 4 + t][128 * s + j0]);
#pragma unroll
                    for (int r = 0; r < 8; ++r) {
                        unsigned long long aa = pkdup(reinterpret_cast<const float*>(&a4[r])[t]);
#pragma unroll
                        for (int s = 0; s < 4; ++s)
                            fma2(acc2[r][s], aa, w2[s]);
                    }
                }
            }

            // store prefetched chunk into the other buffer
            if (ch < NCHUNK - 1) {
#pragma unroll
                for (int i = 0; i < 4; ++i) {
                    Ws[buf ^ 1][wkf * 4 + 0][wg[i]] = wreg[i].x;
                    Ws[buf ^ 1][wkf * 4 + 1][wg[i]] = wreg[i].y;
                    Ws[buf ^ 1][wkf * 4 + 2][wg[i]] = wreg[i].z;
                    Ws[buf ^ 1][wkf * 4 + 3][wg[i]] = wreg[i].w;
                }
            }
            __syncthreads();
        }
    }

    // ---- LSTM cell update (thread-local, float2-coalesced h/c) ----
    const bool do_fc = (Wfc != nullptr);
    float wfc00 = 0.f, wfc01 = 0.f, wfc10 = 0.f, wfc11 = 0.f;
    if (do_fc) {
        float2 wa = *reinterpret_cast<const float2*>(&Wfc[j0]);        // row 0 of Wfc
        float2 wb = *reinterpret_cast<const float2*>(&Wfc[HH + j0]);   // row 1 of Wfc
        wfc00 = wa.x; wfc01 = wa.y; wfc10 = wb.x; wfc11 = wb.y;
    }
    // FC partial scratch aliased onto As (safe: GEMM's final __syncthreads done; re-synced below)
    float* sFC = &As[0][0];   // [8 warps][8 rows][2 dims]

#pragma unroll
    for (int r = 0; r < 8; ++r) {
        int b = row0 + rg * 8 + r;
        size_t idx = (size_t)b * HH + j0;
        float2 cold;
        if (first) cold = make_float2(0.f, 0.f);
        else       cold = *reinterpret_cast<const float2*>(&p.c[idx]);

        float ga[4][2];
#pragma unroll
        for (int s = 0; s < 4; ++s)
            upk2(acc2[r][s], ga[s][0], ga[s][1]);

        float cn0, cn1, hv0, hv1;
        {
            float iv = sigmoidf_(ga[0][0]);
            float fv = sigmoidf_(ga[1][0]);
            float gv = tanhf(ga[2][0]);
            float ov = sigmoidf_(ga[3][0]);
            cn0 = fv * cold.x + iv * gv;
            hv0 = ov * tanhf(cn0);
        }
        {
            float iv = sigmoidf_(ga[0][1]);
            float fv = sigmoidf_(ga[1][1]);
            float gv = tanhf(ga[2][1]);
            float ov = sigmoidf_(ga[3][1]);
            cn1 = fv * cold.y + iv * gv;
            hv1 = ov * tanhf(cn1);
        }
        *reinterpret_cast<float2*>(&p.c[idx]) = make_float2(cn0, cn1);
        *reinterpret_cast<float2*>(&p.h[idx]) = make_float2(hv0, hv1);

        if (do_fc) {
            float f0 = hv0 * wfc00 + hv1 * wfc01;   // partial over this warp's 64 hidden
            float f1 = hv0 * wfc10 + hv1 * wfc11;
#pragma unroll
            for (int off = 16; off > 0; off >>= 1) {
                f0 += __shfl_xor_sync(0xffffffffu, f0, off);
                f1 += __shfl_xor_sync(0xffffffffu, f1, off);
            }
            if (lane == 0) {
                sFC[(warp * 8 + r) * 2 + 0] = f0;
                sFC[(warp * 8 + r) * 2 + 1] = f1;
            }
        }
    }

    if (do_fc) {
        __syncthreads();
        // combine warp-pair partials: output (rg2, r, d); warps (2*rg2, 2*rg2+1)
        if (tid < 64) {
            int rg2 = tid >> 4;        // 0..3
            int r   = (tid >> 1) & 7;  // 0..7
            int d   = tid & 1;
            float v = sFC[((2 * rg2) * 8 + r) * 2 + d]
                    + sFC[((2 * rg2 + 1) * 8 + r) * 2 + d]
                    + bfc[d];
            int b = row0 + rg2 * 8 + r;
            p.fc_state[b * 2 + d] = v;
            p.fc_out[b * 2 + d]   = v;
        }
    }
}

// warp-per-row layernorm over 4 state arrays + decoder state combine + seed copy
__device__ __forceinline__ float4 ln4(float4 v, float4 gg, float4 bb) {
    float s  = v.x + v.y + v.z + v.w;
    float ss = v.x * v.x + v.y * v.y + v.z * v.z + v.w * v.w;
#pragma unroll
    for (int off = 16; off > 0; off >>= 1) {
        s  += __shfl_xor_sync(0xffffffffu, s, off);
        ss += __shfl_xor_sync(0xffffffffu, ss, off);
    }
    float m   = s * (1.0f / HH);
    float var = ss * (1.0f / HH) - m * m;
    float inv = rsqrtf(var + 1e-5f);
    float4 r;
    r.x = (v.x - m) * inv * gg.x + bb.x;
    r.y = (v.y - m) * inv * gg.y + bb.y;
    r.z = (v.z - m) * inv * gg.z + bb.z;
    r.w = (v.w - m) * inv * gg.w + bb.w;
    return r;
}

__global__ __launch_bounds__(NTHREADS)
void ln_combine_kernel(const float* __restrict__ ln_g, const float* __restrict__ ln_b,
                       const float* __restrict__ speed_last, const float* __restrict__ pos_last)
{
    const int tid = threadIdx.x;
    const int warp = tid >> 5;
    const int lane = tid & 31;
    const int b = blockIdx.x * 8 + warp;

    // seed decoder inputs: cs = speed[-1], cp = pos[-1]
    if (tid < 16) {
        int rb = blockIdx.x * 8 + (tid >> 1);
        g_cs[rb * 2 + (tid & 1)] = speed_last[rb * 2 + (tid & 1)];
    } else if (tid < 32) {
        int t2 = tid - 16;
        int rb = blockIdx.x * 8 + (t2 >> 1);
        g_cp[rb * 2 + (t2 & 1)] = pos_last[rb * 2 + (t2 & 1)];
    }

    size_t base = (size_t)b * HH + lane * 4;
    float4 gg = *reinterpret_cast<const float4*>(&ln_g[lane * 4]);
    float4 gb = *reinterpret_cast<const float4*>(&ln_b[lane * 4]);

    float4 hpo = ln4(*reinterpret_cast<const float4*>(&g_hpo[base]), gg, gb);
    float4 cpo = ln4(*reinterpret_cast<const float4*>(&g_cpo[base]), gg, gb);
    float4 hsp = ln4(*reinterpret_cast<const float4*>(&g_hsp[base]), gg, gb);
    float4 csp = ln4(*reinterpret_cast<const float4*>(&g_csp[base]), gg, gb);

    *reinterpret_cast<float4*>(&g_hpo[base]) = hpo;
    *reinterpret_cast<float4*>(&g_cpo[base]) = cpo;
    float4 hds = make_float4(hpo.x + hsp.x, hpo.y + hsp.y, hpo.z + hsp.z, hpo.w + hsp.w);
    float4 cds = make_float4(cpo.x + csp.x, cpo.y + csp.y, cpo.z + csp.z, cpo.w + csp.w);
    *reinterpret_cast<float4*>(&g_hds[base]) = hds;
    *reinterpret_cast<float4*>(&g_cds[base]) = cds;
}

extern "C" void kernel_launch(void* const* d_in, const int* in_sizes, int n_in,
                              void* d_out, int out_size)
{
    const float* pos    = (const float*)d_in[0];
    const float* speed  = (const float*)d_in[1];
    const float* Wih_pe = (const float*)d_in[2];
    const float* Whh_pe = (const float*)d_in[3];
    const float* bih_pe = (const float*)d_in[4];
    const float* bhh_pe = (const float*)d_in[5];
    const float* Wih_se = (const float*)d_in[6];
    const float* Whh_se = (const float*)d_in[7];
    const float* bih_se = (const float*)d_in[8];
    const float* bhh_se = (const float*)d_in[9];
    const float* ln_g   = (const float*)d_in[10];
    const float* ln_b   = (const float*)d_in[11];
    const float* Wih_sd = (const float*)d_in[12];
    const float* Whh_sd = (const float*)d_in[13];
    const float* bih_sd = (const float*)d_in[14];
    const float* bhh_sd = (const float*)d_in[15];
    const float* Wih_pd = (const float*)d_in[16];
    const float* Whh_pd = (const float*)d_in[17];
    const float* bih_pd = (const float*)d_in[18];
    const float* bhh_pd = (const float*)d_in[19];
    const float* Wfc    = (const float*)d_in[20];
    const float* bfc    = (const float*)d_in[21];

    float* out = (float*)d_out;
    float* pos_out = out;                              // [PRED, B, 2]
    float* speed_out = out + (size_t)PRED * BB * 2;    // [PRED, B, 2]

    float *hpo, *cpo, *hsp, *csp, *hds, *cds, *cs, *cp;
    cudaGetSymbolAddress((void**)&hpo, g_hpo);
    cudaGetSymbolAddress((void**)&cpo, g_cpo);
    cudaGetSymbolAddress((void**)&hsp, g_hsp);
    cudaGetSymbolAddress((void**)&csp, g_csp);
    cudaGetSymbolAddress((void**)&hds, g_hds);
    cudaGetSymbolAddress((void**)&cds, g_cds);
    cudaGetSymbolAddress((void**)&cs,  g_cs);
    cudaGetSymbolAddress((void**)&cp,  g_cp);

    dim3 grid(BB / MT, 2);

    // ---- encoders (pos + speed fused per launch) ----
    for (int t = 0; t < TT; ++t) {
        StepParams pe { pos   + (size_t)t * BB * 2, Wih_pe, Whh_pe, bih_pe, bhh_pe, hpo, cpo, nullptr, nullptr };
        StepParams se { speed + (size_t)t * BB * 2, Wih_se, Whh_se, bih_se, bhh_se, hsp, csp, nullptr, nullptr };
        lstm_step_kernel<<<grid, NTHREADS>>>(pe, se, nullptr, nullptr, (t == 0) ? 1 : 0);
    }

    // ---- layernorm + decoder-state combine + seed cs/cp ----
    ln_combine_kernel<<<BB / 8, NTHREADS>>>(ln_g, ln_b,
                                            speed + (size_t)(TT - 1) * BB * 2,
                                            pos   + (size_t)(TT - 1) * BB * 2);

    // ---- decoder (speed cell + pos cell fused per launch, FC fused) ----
    for (int t = 0; t < PRED; ++t) {
        StepParams sd { cs, Wih_sd, Whh_sd, bih_sd, bhh_sd, hds, cds, cs, speed_out + (size_t)t * BB * 2 };
        StepParams pd { cp, Wih_pd, Whh_pd, bih_pd, bhh_pd, hpo, cpo, cp, pos_out   + (size_t)t * BB * 2 };
        lstm_step_kernel<<<grid, NTHREADS>>>(sd, pd, Wfc, bfc, 0);
    }
}

// round 15
// speedup vs baseline: 2.1689x; 2.1689x over previous
#include <cuda_runtime.h>
#include <cuda_bf16.h>
#include <math.h>
#include <stdint.h>

#define BB 16384
#define HH 128
#define TT 20
#define PRED 30

#define MROWS 128
#define NTH 256

// ---------------- persistent state ----------------
__device__ float g_hpo[BB * HH];
__device__ float g_cpo[BB * HH];
__device__ float g_hsp[BB * HH];
__device__ float g_csp[BB * HH];
__device__ float g_hds[BB * HH];
__device__ float g_cds[BB * HH];
__device__ float g_cs[BB * 2];
__device__ float g_cp[BB * 2];

// fragment-packed bf16 weights: [mat][ s*4096 + hg*1024 + sub*256 + kk*32 + lane ]
// each uint4 = { Whi(k0,k0+1), Whi(k0+8,k0+9), Wlo(k0,k0+1), Wlo(k0+8,k0+9) } for n = nt*8+grp
__device__ __align__(16) uint4 g_Wpack[4][16384];

__device__ __forceinline__ float sigmoidf_(float x) { return 1.0f / (1.0f + expf(-x)); }

__device__ __forceinline__ uint32_t bf2_hi(float a, float b, float& ra, float& rb) {
    __nv_bfloat162 hp = __floats2bfloat162_rn(a, b);
    ra = a - __bfloat162float(hp.x);
    rb = b - __bfloat162float(hp.y);
    return *reinterpret_cast<uint32_t*>(&hp);
}
__device__ __forceinline__ uint32_t bf2(float a, float b) {
    __nv_bfloat162 v = __floats2bfloat162_rn(a, b);
    return *reinterpret_cast<uint32_t*>(&v);
}

// m16n8k16 row.col f32.bf16.bf16.f32
__device__ __forceinline__ void mma16816(float* c, const uint32_t* a, uint32_t b0, uint32_t b1) {
    asm volatile(
        "mma.sync.aligned.m16n8k16.row.col.f32.bf16.bf16.f32 "
        "{%0,%1,%2,%3}, {%4,%5,%6,%7}, {%8,%9}, {%0,%1,%2,%3};\n"
        : "+f"(c[0]), "+f"(c[1]), "+f"(c[2]), "+f"(c[3])
        : "r"(a[0]), "r"(a[1]), "r"(a[2]), "r"(a[3]), "r"(b0), "r"(b1));
}

// ---------------- prep: fp32 W[512][128] -> fragment-packed bf16 hi/lo ----------------
__global__ void prep_w_kernel(const float* __restrict__ w0, const float* __restrict__ w1,
                              const float* __restrict__ w2, const float* __restrict__ w3)
{
    int idx = blockIdx.x * 256 + threadIdx.x;       // 65536 total
    int mat = idx >> 14;
    int rem = idx & 16383;
    int nt   = rem >> 8;        // 0..63  (n-tile of 8)
    int kk   = (rem >> 5) & 7;  // 0..7   (k-step of 16)
    int lane = rem & 31;
    int grp = lane >> 2, tig = lane & 3;
    const float* W = (mat == 0) ? w0 : (mat == 1) ? w1 : (mat == 2) ? w2 : w3;

    int n  = nt * 8 + grp;
    int k0 = kk * 16 + 2 * tig;
    float w00 = W[n * HH + k0],     w01 = W[n * HH + k0 + 1];
    float w10 = W[n * HH + k0 + 8], w11 = W[n * HH + k0 + 9];

    float r00, r01, r10, r11;
    uint32_t h01 = bf2_hi(w00, w01, r00, r01);
    uint32_t h89 = bf2_hi(w10, w11, r10, r11);
    uint32_t l01 = bf2(r00, r01);
    uint32_t l89 = bf2(r10, r11);

    // index in fragment order: nt = s*16 + hg*4 + sub  ->  s*4096 + hg*1024 + sub*256 + kk*32 + lane
    int s   = nt >> 4;
    int hg  = (nt >> 2) & 3;
    int sub = nt & 3;
    g_Wpack[mat][s * 4096 + hg * 1024 + sub * 256 + kk * 32 + lane] = make_uint4(h01, h89, l01, l89);
}

// ---------------- mma.sync LSTM step ----------------
struct MParams {
    const float* x;        // [B,2]
    const float* bih;      // [512]
    const float* bhh;      // [512]
    const float* Wih;      // [512,2]
    float* h;              // [B,128]
    float* c;              // [B,128]
    float* fc_state;       // decoder next-input [B,2] or null
    float* fc_out;         // decoder output slice [B,2] or null
    int mat;
};

__global__ __launch_bounds__(NTH, 1)
void lstm_mma_step(MParams pa, MParams pb, const float* __restrict__ Wfc,
                   const float* __restrict__ bfc, int first)
{
    const MParams p = blockIdx.y ? pb : pa;

    __shared__ float  s_bc[512];    // bih + bhh
    __shared__ float2 s_wih[512];   // Wih rows
    __shared__ float  s_wfc[260];   // 256 Wfc + bfc[2]

    const int tid  = threadIdx.x;
    const int lane = tid & 31;
    const int wg   = tid >> 5;        // 8 warps, 16 rows each
    const int grp  = lane >> 2;       // 0..7
    const int tig  = lane & 3;        // 0..3
    const int row0 = blockIdx.x * MROWS;
    const int r_a  = row0 + wg * 16 + grp;
    const int r_b  = r_a + 8;

    // ---- stage consts ----
    if (tid < 128) {
        float4 bi = reinterpret_cast<const float4*>(p.bih)[tid];
        float4 bh = reinterpret_cast<const float4*>(p.bhh)[tid];
        reinterpret_cast<float4*>(s_bc)[tid] = make_float4(bi.x + bh.x, bi.y + bh.y, bi.z + bh.z, bi.w + bh.w);
    }
    reinterpret_cast<float4*>(s_wih)[tid] = reinterpret_cast<const float4*>(p.Wih)[tid];
    const bool do_fc = (p.fc_out != nullptr);
    if (do_fc) {
        if (tid < 64)
            reinterpret_cast<float4*>(s_wfc)[tid] = reinterpret_cast<const float4*>(Wfc)[tid];
        if (tid == 0) { s_wfc[256] = bfc[0]; s_wfc[257] = bfc[1]; }
    }
    __syncthreads();

    // ---- A fragments (hi/lo) for this warp's 2 rows, K=128 ----
    uint32_t ahi[8][4], alo[8][4];
    if (!first) {
        const float* ha = p.h + (size_t)r_a * HH;
        const float* hb = p.h + (size_t)r_b * HH;
#pragma unroll
        for (int m = 0; m < 16; ++m) {
            float2 va = *reinterpret_cast<const float2*>(ha + 2 * tig + 8 * m);
            float2 vb = *reinterpret_cast<const float2*>(hb + 2 * tig + 8 * m);
            int kk = m >> 1;
            int sa = (m & 1) ? 2 : 0;   // row-a slot
            int sb = sa + 1;            // row-b slot
            float ra0, ra1, rb0, rb1;
            ahi[kk][sa] = bf2_hi(va.x, va.y, ra0, ra1);
            ahi[kk][sb] = bf2_hi(vb.x, vb.y, rb0, rb1);
            alo[kk][sa] = bf2(ra0, ra1);
            alo[kk][sb] = bf2(rb0, rb1);
        }
    }

    const float2 xa = *reinterpret_cast<const float2*>(&p.x[r_a * 2]);
    const float2 xb = *reinterpret_cast<const float2*>(&p.x[r_b * 2]);
    float fc0a = 0.f, fc1a = 0.f, fc0b = 0.f, fc1b = 0.f;
    const uint4* wp = g_Wpack[p.mat];

    for (int hg = 0; hg < 4; ++hg) {
        float acc[16][4];
#pragma unroll
        for (int i = 0; i < 16; ++i)
#pragma unroll
            for (int j = 0; j < 4; ++j) acc[i][j] = 0.f;

        if (!first) {
#pragma unroll
            for (int kk = 0; kk < 8; ++kk) {
#pragma unroll
                for (int s = 0; s < 4; ++s) {
#pragma unroll
                    for (int sub = 0; sub < 4; ++sub) {
                        uint4 w = wp[s * 4096 + hg * 1024 + sub * 256 + kk * 32 + lane];
                        float* c4 = acc[s * 4 + sub];
                        mma16816(c4, ahi[kk], w.x, w.y);   // Ahi * Whi
                        mma16816(c4, alo[kk], w.x, w.y);   // Alo * Whi
                        mma16816(c4, ahi[kk], w.z, w.w);   // Ahi * Wlo
                    }
                }
            }
        }

        // ---- epilogue for this hidden group ----
#pragma unroll
        for (int sub = 0; sub < 4; ++sub) {
            const int j0 = hg * 32 + sub * 8 + 2 * tig;
            float2 ca = make_float2(0.f, 0.f), cb = make_float2(0.f, 0.f);
            if (!first) {
                ca = *reinterpret_cast<const float2*>(&p.c[(size_t)r_a * HH + j0]);
                cb = *reinterpret_cast<const float2*>(&p.c[(size_t)r_b * HH + j0]);
            }
            float2 cna, hna, cnb, hnb;
#pragma unroll
            for (int d = 0; d < 2; ++d) {
                const int j = j0 + d;
                // row a
                {
                    float gi = acc[0 * 4 + sub][d]  + s_bc[j]       + xa.x * s_wih[j].x       + xa.y * s_wih[j].y;
                    float gf = acc[1 * 4 + sub][d]  + s_bc[128 + j] + xa.x * s_wih[128 + j].x + xa.y * s_wih[128 + j].y;
                    float gg = acc[2 * 4 + sub][d]  + s_bc[256 + j] + xa.x * s_wih[256 + j].x + xa.y * s_wih[256 + j].y;
                    float go = acc[3 * 4 + sub][d]  + s_bc[384 + j] + xa.x * s_wih[384 + j].x + xa.y * s_wih[384 + j].y;
                    float iv = sigmoidf_(gi), fv = sigmoidf_(gf), gv = tanhf(gg), ov = sigmoidf_(go);
                    float cold = d ? ca.y : ca.x;
                    float cn = fv * cold + iv * gv;
                    float hn = ov * tanhf(cn);
                    if (d) { cna.y = cn; hna.y = hn; } else { cna.x = cn; hna.x = hn; }
                    if (do_fc) { fc0a = fmaf(hn, s_wfc[j], fc0a); fc1a = fmaf(hn, s_wfc[128 + j], fc1a); }
                }
                // row b
                {
                    float gi = acc[0 * 4 + sub][2 + d] + s_bc[j]       + xb.x * s_wih[j].x       + xb.y * s_wih[j].y;
                    float gf = acc[1 * 4 + sub][2 + d] + s_bc[128 + j] + xb.x * s_wih[128 + j].x + xb.y * s_wih[128 + j].y;
                    float gg = acc[2 * 4 + sub][2 + d] + s_bc[256 + j] + xb.x * s_wih[256 + j].x + xb.y * s_wih[256 + j].y;
                    float go = acc[3 * 4 + sub][2 + d] + s_bc[384 + j] + xb.x * s_wih[384 + j].x + xb.y * s_wih[384 + j].y;
                    float iv = sigmoidf_(gi), fv = sigmoidf_(gf), gv = tanhf(gg), ov = sigmoidf_(go);
                    float cold = d ? cb.y : cb.x;
                    float cn = fv * cold + iv * gv;
                    float hn = ov * tanhf(cn);
                    if (d) { cnb.y = cn; hnb.y = hn; } else { cnb.x = cn; hnb.x = hn; }
                    if (do_fc) { fc0b = fmaf(hn, s_wfc[j], fc0b); fc1b = fmaf(hn, s_wfc[128 + j], fc1b); }
                }
            }
            *reinterpret_cast<float2*>(&p.c[(size_t)r_a * HH + j0]) = cna;
            *reinterpret_cast<float2*>(&p.h[(size_t)r_a * HH + j0]) = hna;
            *reinterpret_cast<float2*>(&p.c[(size_t)r_b * HH + j0]) = cnb;
            *reinterpret_cast<float2*>(&p.h[(size_t)r_b * HH + j0]) = hnb;
        }
    }

    if (do_fc) {
        // reduce over the 4 lanes of each quad (tig axis)
#pragma unroll
        for (int off = 1; off <= 2; off <<= 1) {
            fc0a += __shfl_xor_sync(0xffffffffu, fc0a, off);
            fc1a += __shfl_xor_sync(0xffffffffu, fc1a, off);
            fc0b += __shfl_xor_sync(0xffffffffu, fc0b, off);
            fc1b += __shfl_xor_sync(0xffffffffu, fc1b, off);
        }
        if (tig == 0) {
            float oa0 = fc0a + s_wfc[256], oa1 = fc1a + s_wfc[257];
            float ob0 = fc0b + s_wfc[256], ob1 = fc1b + s_wfc[257];
            p.fc_state[r_a * 2 + 0] = oa0; p.fc_state[r_a * 2 + 1] = oa1;
            p.fc_out[r_a * 2 + 0]   = oa0; p.fc_out[r_a * 2 + 1]   = oa1;
            p.fc_state[r_b * 2 + 0] = ob0; p.fc_state[r_b * 2 + 1] = ob1;
            p.fc_out[r_b * 2 + 0]   = ob0; p.fc_out[r_b * 2 + 1]   = ob1;
        }
    }
}

// ---------------- layernorm + combine ----------------
__device__ __forceinline__ float4 ln4(float4 v, float4 gg, float4 bb) {
    float s  = v.x + v.y + v.z + v.w;
    float ss = v.x * v.x + v.y * v.y + v.z * v.z + v.w * v.w;
#pragma unroll
    for (int off = 16; off > 0; off >>= 1) {
        s  += __shfl_xor_sync(0xffffffffu, s, off);
        ss += __shfl_xor_sync(0xffffffffu, ss, off);
    }
    float m   = s * (1.0f / HH);
    float var = ss * (1.0f / HH) - m * m;
    float inv = rsqrtf(var + 1e-5f);
    float4 r;
    r.x = (v.x - m) * inv * gg.x + bb.x;
    r.y = (v.y - m) * inv * gg.y + bb.y;
    r.z = (v.z - m) * inv * gg.z + bb.z;
    r.w = (v.w - m) * inv * gg.w + bb.w;
    return r;
}

__global__ __launch_bounds__(256)
void ln_combine_kernel(const float* __restrict__ ln_g, const float* __restrict__ ln_b,
                       const float* __restrict__ speed_last, const float* __restrict__ pos_last)
{
    const int tid = threadIdx.x;
    const int warp = tid >> 5;
    const int lane = tid & 31;
    const int b = blockIdx.x * 8 + warp;

    if (tid < 16) {
        int rb = blockIdx.x * 8 + (tid >> 1);
        g_cs[rb * 2 + (tid & 1)] = speed_last[rb * 2 + (tid & 1)];
    } else if (tid < 32) {
        int t2 = tid - 16;
        int rb = blockIdx.x * 8 + (t2 >> 1);
        g_cp[rb * 2 + (t2 & 1)] = pos_last[rb * 2 + (t2 & 1)];
    }

    size_t base = (size_t)b * HH + lane * 4;
    float4 gg = *reinterpret_cast<const float4*>(&ln_g[lane * 4]);
    float4 gb = *reinterpret_cast<const float4*>(&ln_b[lane * 4]);

    float4 hpo = ln4(*reinterpret_cast<const float4*>(&g_hpo[base]), gg, gb);
    float4 cpo = ln4(*reinterpret_cast<const float4*>(&g_cpo[base]), gg, gb);
    float4 hsp = ln4(*reinterpret_cast<const float4*>(&g_hsp[base]), gg, gb);
    float4 csp = ln4(*reinterpret_cast<const float4*>(&g_csp[base]), gg, gb);

    *reinterpret_cast<float4*>(&g_hpo[base]) = hpo;
    *reinterpret_cast<float4*>(&g_cpo[base]) = cpo;
    float4 hds = make_float4(hpo.x + hsp.x, hpo.y + hsp.y, hpo.z + hsp.z, hpo.w + hsp.w);
    float4 cds = make_float4(cpo.x + csp.x, cpo.y + csp.y, cpo.z + csp.z, cpo.w + csp.w);
    *reinterpret_cast<float4*>(&g_hds[base]) = hds;
    *reinterpret_cast<float4*>(&g_cds[base]) = cds;
}

// ---------------- host ----------------
extern "C" void kernel_launch(void* const* d_in, const int* in_sizes, int n_in,
                              void* d_out, int out_size)
{
    const float* pos    = (const float*)d_in[0];
    const float* speed  = (const float*)d_in[1];
    const float* Wih_pe = (const float*)d_in[2];
    const float* Whh_pe = (const float*)d_in[3];
    const float* bih_pe = (const float*)d_in[4];
    const float* bhh_pe = (const float*)d_in[5];
    const float* Wih_se = (const float*)d_in[6];
    const float* Whh_se = (const float*)d_in[7];
    const float* bih_se = (const float*)d_in[8];
    const float* bhh_se = (const float*)d_in[9];
    const float* ln_g   = (const float*)d_in[10];
    const float* ln_b   = (const float*)d_in[11];
    const float* Wih_sd = (const float*)d_in[12];
    const float* Whh_sd = (const float*)d_in[13];
    const float* bih_sd = (const float*)d_in[14];
    const float* bhh_sd = (const float*)d_in[15];
    const float* Wih_pd = (const float*)d_in[16];
    const float* Whh_pd = (const float*)d_in[17];
    const float* bih_pd = (const float*)d_in[18];
    const float* bhh_pd = (const float*)d_in[19];
    const float* Wfc    = (const float*)d_in[20];
    const float* bfc    = (const float*)d_in[21];

    float* out = (float*)d_out;
    float* pos_out = out;
    float* speed_out = out + (size_t)PRED * BB * 2;

    float *hpo, *cpo, *hsp, *csp, *hds, *cds, *cs, *cp;
    cudaGetSymbolAddress((void**)&hpo, g_hpo);
    cudaGetSymbolAddress((void**)&cpo, g_cpo);
    cudaGetSymbolAddress((void**)&hsp, g_hsp);
    cudaGetSymbolAddress((void**)&csp, g_csp);
    cudaGetSymbolAddress((void**)&hds, g_hds);
    cudaGetSymbolAddress((void**)&cds, g_cds);
    cudaGetSymbolAddress((void**)&cs,  g_cs);
    cudaGetSymbolAddress((void**)&cp,  g_cp);

    // weight fragment images (every call; deterministic)
    prep_w_kernel<<<256, 256>>>(Whh_pe, Whh_se, Whh_sd, Whh_pd);

    dim3 grid(BB / MROWS, 2);

    // encoders: a = pos (mat 0), b = speed (mat 1)
    for (int t = 0; t < TT; ++t) {
        MParams pe { pos   + (size_t)t * BB * 2, bih_pe, bhh_pe, Wih_pe, hpo, cpo, nullptr, nullptr, 0 };
        MParams se { speed + (size_t)t * BB * 2, bih_se, bhh_se, Wih_se, hsp, csp, nullptr, nullptr, 1 };
        lstm_mma_step<<<grid, NTH>>>(pe, se, Wfc, bfc, (t == 0) ? 1 : 0);
    }

    ln_combine_kernel<<<BB / 8, 256>>>(ln_g, ln_b,
                                       speed + (size_t)(TT - 1) * BB * 2,
                                       pos   + (size_t)(TT - 1) * BB * 2);

    // decoders: a = speed-decoder (mat 2), b = pos-decoder (mat 3)
    for (int t = 0; t < PRED; ++t) {
        MParams sd { cs, bih_sd, bhh_sd, Wih_sd, hds, cds, cs, speed_out + (size_t)t * BB * 2, 2 };
        MParams pd { cp, bih_pd, bhh_pd, Wih_pd, hpo, cpo, cp, pos_out   + (size_t)t * BB * 2, 3 };
        lstm_mma_step<<<grid, NTH>>>(sd, pd, Wfc, bfc, 0);
    }
}